// round 1
// baseline (speedup 1.0000x reference)
#include <cuda_runtime.h>
#include <math.h>

#define Nn 50000
#define Ee 800000
#define Gg 64
#define Ff 6
#define Hh 256
#define Oo 2
#define NEx 8
#define NH (Nn*Hh)

// ---------------- scratch (static __device__ arrays; no allocation) ----------------
__device__ __align__(128) float g_h[NH];          // encoder output
__device__ __align__(128) float g_r[NH];          // router hidden
__device__ __align__(128) float g_he[NEx*NH];     // per-expert activations
__device__ __align__(128) float g_t[NEx*NH];      // he @ Wr   (also router GEMM scratch)
__device__ __align__(128) float g_v[NEx*NH];      // he @ Wn
__device__ __align__(128) float g_agg[NEx*NH];    // A @ v
__device__ __align__(128) float g_sf[Nn*2];
__device__ __align__(128) float g_logits[Nn*NEx];
__device__ __align__(128) float g_sparse[Nn*NEx];
__device__ __align__(128) float g_mz[NEx*Nn*4];   // [m0,m1,z0,z1] per (e,node)
__device__ __align__(128) float g_aggz[NEx*Nn*2];
__device__ int g_nodecnt[Gg];
__device__ int g_edgecnt[Gg];
__device__ int g_indeg[Nn];
__device__ int g_scantmp[Nn];
__device__ int g_bsum[64];
__device__ int g_bsumscan[64];
__device__ int g_rowstart[Nn+1];
__device__ int g_cursor[Nn];
__device__ int g_csr_src[Ee];

// ---------------- small kernels ----------------
__global__ void k_zero() {
    int i = blockIdx.x*blockDim.x + threadIdx.x;
    if (i < Gg) { g_nodecnt[i]=0; g_edgecnt[i]=0; }
    if (i < Nn) g_indeg[i]=0;
}

__global__ void k_encoder(const float* __restrict__ x, const float* __restrict__ W,
                          const float* __restrict__ b) {
    int idx = blockIdx.x*blockDim.x + threadIdx.x;
    if (idx >= NH) return;
    int i = idx >> 8, c = idx & 255;
    float acc = b[c];
#pragma unroll
    for (int k=0;k<Ff;k++) acc += x[i*Ff+k]*W[k*Hh+c];
    g_h[idx] = fmaxf(acc, 0.f);
}

__global__ void k_count_nodes(const int* __restrict__ batch) {
    __shared__ int hist[Gg];
    int t = threadIdx.x;
    if (t < Gg) hist[t]=0;
    __syncthreads();
    for (int i = blockIdx.x*blockDim.x + t; i < Nn; i += gridDim.x*blockDim.x)
        atomicAdd(&hist[batch[i]], 1);
    __syncthreads();
    if (t < Gg) atomicAdd(&g_nodecnt[t], hist[t]);
}

__global__ void k_count_edges(const int* __restrict__ ei, const int* __restrict__ batch) {
    __shared__ int hist[Gg];
    int t = threadIdx.x;
    if (t < Gg) hist[t]=0;
    __syncthreads();
    for (int e = blockIdx.x*blockDim.x + t; e < Ee; e += gridDim.x*blockDim.x)
        atomicAdd(&hist[batch[ei[e]]], 1);
    __syncthreads();
    if (t < Gg) atomicAdd(&g_edgecnt[t], hist[t]);
}

__global__ void k_indeg(const int* __restrict__ ei) {
    int e = blockIdx.x*blockDim.x + threadIdx.x;
    if (e < Ee) atomicAdd(&g_indeg[ei[Ee+e]], 1);
}

__global__ void k_sizefeat(const int* __restrict__ batch) {
    int i = blockIdx.x*blockDim.x + threadIdx.x;
    if (i >= Nn) return;
    int g = batch[i];
    g_sf[i*2+0] = logf((float)g_nodecnt[g] + 1.f);
    g_sf[i*2+1] = logf((float)g_edgecnt[g] + 1.f);
}

__global__ void k_scan1() {
    __shared__ int sh[1024];
    int t = threadIdx.x, gid = blockIdx.x*1024 + t;
    sh[t] = (gid < Nn) ? g_indeg[gid] : 0;
    __syncthreads();
    for (int off=1; off<1024; off<<=1) {
        int a = (t>=off) ? sh[t-off] : 0;
        __syncthreads();
        sh[t] += a;
        __syncthreads();
    }
    if (gid < Nn) g_scantmp[gid] = sh[t];
    if (t == 1023) g_bsum[blockIdx.x] = sh[1023];
}

__global__ void k_scan2() {
    __shared__ int sh[64];
    int t = threadIdx.x;
    const int NB1 = (Nn + 1023)/1024;
    sh[t] = (t < NB1) ? g_bsum[t] : 0;
    __syncthreads();
    for (int off=1; off<64; off<<=1) {
        int a = (t>=off) ? sh[t-off] : 0;
        __syncthreads();
        sh[t] += a;
        __syncthreads();
    }
    g_bsumscan[t] = sh[t];
}

__global__ void k_scan3() {
    int i = blockIdx.x*blockDim.x + threadIdx.x;
    if (i >= Nn) return;
    int blk = i >> 10;
    int incl = g_scantmp[i] + (blk ? g_bsumscan[blk-1] : 0);
    g_rowstart[i+1] = incl;
    if (i == 0) g_rowstart[0] = 0;
}

__global__ void k_cursor() {
    int i = blockIdx.x*blockDim.x + threadIdx.x;
    if (i < Nn) g_cursor[i] = g_rowstart[i];
}

__global__ void k_scatter(const int* __restrict__ ei) {
    int e = blockIdx.x*blockDim.x + threadIdx.x;
    if (e >= Ee) return;
    int d = ei[Ee+e];
    int p = atomicAdd(&g_cursor[d], 1);
    g_csr_src[p] = ei[e];
}

// ---------------- tiled fp32 SGEMM: C = A[M,256] @ B[256,Nc] ----------------
// amode: 0 -> A = g_h (shared across z), 1 -> A = g_he + z*NH
// cmode: 0 -> C = g_t, 1 -> C = g_v   (offset z*M*Nc)
__global__ void __launch_bounds__(256) k_sgemm(int amode, const float* __restrict__ B0,
                                               int bStride, int cmode, int M, int Ncols) {
    int e = blockIdx.z;
    const float* A = amode ? (g_he + (size_t)e*NH) : g_h;
    const float* B = B0 + (size_t)e*bStride;
    float* Cb = (cmode ? g_v : g_t) + (size_t)e*(size_t)M*Ncols;

    __shared__ float As[16][128];   // transposed: As[k][m]
    __shared__ float Bs[16][128];   // Bs[k][n]

    int tid = threadIdx.x;
    int bm = blockIdx.x*128, bn = blockIdx.y*128;
    int tx = tid & 15, ty = tid >> 4;
    int a_row = tid >> 2;
    int a_col = (tid & 3) * 4;
    int b_row = tid >> 5;
    int b_col = (tid & 31) * 4;

    float acc[8][8];
#pragma unroll
    for (int i=0;i<8;i++)
#pragma unroll
        for (int j=0;j<8;j++) acc[i][j]=0.f;

    for (int kt=0; kt<256; kt+=16) {
        __syncthreads();
#pragma unroll
        for (int i=0;i<2;i++) {
            int r = a_row + i*64;
            int gm = bm + r;
            float4 av = make_float4(0.f,0.f,0.f,0.f);
            if (gm < M) av = *(const float4*)(A + (size_t)gm*256 + kt + a_col);
            As[a_col+0][r]=av.x; As[a_col+1][r]=av.y;
            As[a_col+2][r]=av.z; As[a_col+3][r]=av.w;
        }
#pragma unroll
        for (int i=0;i<2;i++) {
            int r = b_row + i*8;
            *(float4*)&Bs[r][b_col] = *(const float4*)(B + (size_t)(kt+r)*Ncols + bn + b_col);
        }
        __syncthreads();
#pragma unroll
        for (int kk=0;kk<16;kk++) {
            float4 a0 = *(const float4*)&As[kk][ty*4];
            float4 a1 = *(const float4*)&As[kk][64+ty*4];
            float4 b0 = *(const float4*)&Bs[kk][tx*4];
            float4 b1 = *(const float4*)&Bs[kk][64+tx*4];
            float a[8] = {a0.x,a0.y,a0.z,a0.w,a1.x,a1.y,a1.z,a1.w};
            float b[8] = {b0.x,b0.y,b0.z,b0.w,b1.x,b1.y,b1.z,b1.w};
#pragma unroll
            for (int i=0;i<8;i++)
#pragma unroll
                for (int j=0;j<8;j++) acc[i][j] += a[i]*b[j];
        }
    }
#pragma unroll
    for (int ih=0; ih<2; ih++) {
#pragma unroll
        for (int i=0;i<4;i++) {
            int gm = bm + ih*64 + ty*4 + i;
            if (gm >= M) continue;
            float* crow = Cb + (size_t)gm*Ncols + bn;
            int r = ih*4 + i;
            *(float4*)(crow + tx*4)      = make_float4(acc[r][0],acc[r][1],acc[r][2],acc[r][3]);
            *(float4*)(crow + 64 + tx*4) = make_float4(acc[r][4],acc[r][5],acc[r][6],acc[r][7]);
        }
    }
}

// ---------------- router ----------------
__global__ void k_router_epi(const float* __restrict__ W1, const float* __restrict__ b1) {
    int idx = blockIdx.x*blockDim.x + threadIdx.x;
    if (idx >= NH) return;
    int i = idx >> 8, c = idx & 255;
    float v = g_t[idx] + g_sf[i*2]*W1[256*256+c] + g_sf[i*2+1]*W1[257*256+c] + b1[c];
    g_r[idx] = fmaxf(v, 0.f);
}

__global__ void k_logits(const float* __restrict__ W2, const float* __restrict__ b2) {
    int idx = blockIdx.x*blockDim.x + threadIdx.x;
    if (idx >= Nn*NEx) return;
    int i = idx >> 3, e2 = idx & 7;
    const float* r = g_r + (size_t)i*256;
    float acc = b2[e2];
#pragma unroll 8
    for (int k=0;k<256;k++) acc += r[k]*W2[k*8+e2];
    g_logits[idx] = acc;
}

__global__ void k_topk() {
    int i = blockIdx.x*blockDim.x + threadIdx.x;
    if (i >= Nn) return;
    float l[8];
#pragma unroll
    for (int e=0;e<8;e++) l[e] = g_logits[i*8+e];
    int i1 = 0; float m1 = l[0];
#pragma unroll
    for (int e=1;e<8;e++) if (l[e] > m1) { m1 = l[e]; i1 = e; }
    int i2 = -1; float m2 = -1e30f;
#pragma unroll
    for (int e=0;e<8;e++) if (e != i1 && l[e] > m2) { m2 = l[e]; i2 = e; }
    float e2v = expf(m2 - m1);
    float inv = 1.f/(1.f + e2v);
    float s[8];
#pragma unroll
    for (int e=0;e<8;e++) s[e]=0.f;
    s[i1] = inv; s[i2] = e2v*inv;
#pragma unroll
    for (int e=0;e<8;e++) g_sparse[i*8+e] = s[e];
}

// ---------------- SpMM: agg[e,dst,:] = sum_{src in-edges of dst} v[e,src,:] ----------------
__global__ void k_spmm() {
    int dst = blockIdx.x;
    int e = blockIdx.y;
    int t = threadIdx.x;
    const float* vb = g_v + (size_t)e*NH;
    int s0 = g_rowstart[dst], s1 = g_rowstart[dst+1];
    __shared__ int ssrc[256];
    float acc = 0.f;
    for (int base = s0; base < s1; base += 256) {
        int cnt = min(256, s1 - base);
        __syncthreads();
        if (t < cnt) ssrc[t] = g_csr_src[base + t];
        __syncthreads();
#pragma unroll 4
        for (int k=0;k<cnt;k++) acc += vb[(size_t)ssrc[k]*256 + t];
    }
    g_agg[(size_t)e*NH + (size_t)dst*256 + t] = acc;
}

__global__ void k_combine(const float* __restrict__ bias) {
    int idx4 = blockIdx.x*blockDim.x + threadIdx.x;
    if (idx4 >= NEx*NH/4) return;
    int idx = idx4*4;
    int e = idx / NH;
    int c = idx & 255;
    float4 t = *(const float4*)&g_t[idx];
    float4 a = *(const float4*)&g_agg[idx];
    float4 b = *(const float4*)&bias[e*256 + c];
    float4 o;
    o.x = fmaxf(t.x+a.x+b.x, 0.f);
    o.y = fmaxf(t.y+a.y+b.y, 0.f);
    o.z = fmaxf(t.z+a.z+b.z, 0.f);
    o.w = fmaxf(t.w+a.w+b.w, 0.f);
    *(float4*)&g_he[idx] = o;
}

// ---------------- output layer ----------------
__global__ void k_mz(const float* __restrict__ Wr, const float* __restrict__ Wn) {
    int idx = blockIdx.x*blockDim.x + threadIdx.x;
    if (idx >= NEx*Nn*4) return;
    int j = idx & 3;
    int i = (idx >> 2) % Nn;
    int e = (idx >> 2) / Nn;
    const float* he = g_he + (size_t)e*NH + (size_t)i*256;
    const float* W = ((j < 2) ? Wr : Wn) + e*512 + (j & 1);
    float acc = 0.f;
#pragma unroll 8
    for (int k=0;k<256;k++) acc += he[k]*W[k*2];
    g_mz[idx] = acc;
}

__global__ void k_aggz() {
    int idx = blockIdx.x*blockDim.x + threadIdx.x;
    if (idx >= NEx*Nn) return;
    int dst = idx % Nn;
    int e = idx / Nn;
    int s0 = g_rowstart[dst], s1 = g_rowstart[dst+1];
    float a0=0.f, a1=0.f;
    for (int p=s0; p<s1; p++) {
        int src = g_csr_src[p];
        const float* z = g_mz + ((size_t)e*Nn + src)*4 + 2;
        a0 += z[0]; a1 += z[1];
    }
    g_aggz[((size_t)e*Nn+dst)*2+0] = a0;
    g_aggz[((size_t)e*Nn+dst)*2+1] = a1;
}

__global__ void k_final(const float* __restrict__ outb, float* __restrict__ out) {
    int i = blockIdx.x*blockDim.x + threadIdx.x;
    if (i >= Nn) return;
    float o0=0.f, o1=0.f;
#pragma unroll
    for (int e=0;e<8;e++) {
        float s = g_sparse[i*8+e];
        const float* mz = g_mz + ((size_t)e*Nn+i)*4;
        const float* az = g_aggz + ((size_t)e*Nn+i)*2;
        o0 += s*(mz[0] + az[0] + outb[e*2+0]);
        o1 += s*(mz[1] + az[1] + outb[e*2+1]);
    }
    out[i*2+0] = o0;
    out[i*2+1] = o1;
}

// ---------------- launch ----------------
extern "C" void kernel_launch(void* const* d_in, const int* in_sizes, int n_in,
                              void* d_out, int out_size) {
    const float* x    = (const float*)d_in[0];
    const int*   ei   = (const int*)  d_in[1];
    const int*   batch= (const int*)  d_in[2];
    const float* encW = (const float*)d_in[3];
    const float* encb = (const float*)d_in[4];
    const float* rW1  = (const float*)d_in[5];
    const float* rb1  = (const float*)d_in[6];
    const float* rW2  = (const float*)d_in[7];
    const float* rb2  = (const float*)d_in[8];
    const float* hWr  = (const float*)d_in[9];
    const float* hWn  = (const float*)d_in[10];
    const float* hb   = (const float*)d_in[11];
    const float* oWr  = (const float*)d_in[12];
    const float* oWn  = (const float*)d_in[13];
    const float* ob   = (const float*)d_in[14];
    float* out = (float*)d_out;

    k_zero<<<(Nn+255)/256,256>>>();
    k_encoder<<<(NH+255)/256,256>>>(x, encW, encb);
    k_count_nodes<<<256,256>>>(batch);
    k_count_edges<<<512,256>>>(ei, batch);
    k_indeg<<<(Ee+255)/256,256>>>(ei);
    k_sizefeat<<<(Nn+255)/256,256>>>(batch);
    k_scan1<<<(Nn+1023)/1024,1024>>>();
    k_scan2<<<1,64>>>();
    k_scan3<<<(Nn+255)/256,256>>>();
    k_cursor<<<(Nn+255)/256,256>>>();
    k_scatter<<<(Ee+255)/256,256>>>(ei);

    // router
    {
        dim3 gR((Nn+127)/128, 2, 1);
        k_sgemm<<<gR,256>>>(0, rW1, 0, 0, Nn, 256);
        k_router_epi<<<(NH+255)/256,256>>>(rW1, rb1);
        k_logits<<<(Nn*NEx+255)/256,256>>>(rW2, rb2);
        k_topk<<<(Nn+255)/256,256>>>();
    }

    // hidden layers
    dim3 gG((Nn+127)/128, 2, NEx);
    dim3 gS(Nn, NEx, 1);
    int nComb = NEx*NH/4;
    for (int l=0; l<3; l++) {
        int amode = (l==0) ? 0 : 1;
        k_sgemm<<<gG,256>>>(amode, hWr + (size_t)l*NEx*Hh*Hh, Hh*Hh, 0, Nn, 256);
        k_sgemm<<<gG,256>>>(amode, hWn + (size_t)l*NEx*Hh*Hh, Hh*Hh, 1, Nn, 256);
        k_spmm<<<gS,256>>>();
        k_combine<<<(nComb+255)/256,256>>>(hb + (size_t)l*NEx*Hh);
    }

    // output layer: m = he@Wr, z = he@Wn (O=2), aggz = A@z, combine with routing
    k_mz<<<(NEx*Nn*4+255)/256,256>>>(oWr, oWn);
    k_aggz<<<(NEx*Nn+255)/256,256>>>();
    k_final<<<(Nn+255)/256,256>>>(ob, out);
}

// round 6
// speedup vs baseline: 2.1309x; 2.1309x over previous
#include <cuda_runtime.h>
#include <cuda_bf16.h>
#include <cstdint>
#include <math.h>

#define Nn 50000
#define Ee 800000
#define Gg 64
#define Ff 6
#define Hh 256
#define Oo 2
#define NEx 8
#define NH (Nn*Hh)
#define NMATS 49   // 1 router + 3 layers * 8 experts * 2

// ---------------- scratch (static __device__ arrays; no allocation) ----------------
__device__ __align__(128) float g_h[NH];                  // encoder output (fp32, router uses it)
__device__ __align__(128) __nv_bfloat16 g_A0h[NH];        // encoder bf16 hi
__device__ __align__(128) __nv_bfloat16 g_A0l[NH];        // encoder bf16 lo
__device__ __align__(128) float g_r[NH];                  // router hidden
__device__ __align__(128) float g_t[NEx*NH];              // he @ Wr  (router result in [0:NH])
__device__ __align__(128) float g_v[NEx*NH];              // he @ Wn
__device__ __align__(128) __nv_bfloat16 g_Ah[NEx*NH];     // per-expert activation bf16 hi
__device__ __align__(128) __nv_bfloat16 g_Al[NEx*NH];     // per-expert activation bf16 lo
__device__ __align__(128) __nv_bfloat16 g_Wth[NMATS*65536]; // transposed weights bf16 hi  [mat][n][k]
__device__ __align__(128) __nv_bfloat16 g_Wtl[NMATS*65536]; // transposed weights bf16 lo
__device__ __align__(128) float g_sf[Nn*2];
__device__ __align__(128) float g_logits[Nn*NEx];
__device__ __align__(128) float g_sparse[Nn*NEx];
__device__ __align__(128) float g_mz[NEx*Nn*4];           // [m0,m1,z0,z1] per (e,node)
__device__ __align__(128) float g_aggz[NEx*Nn*2];
__device__ int g_nodecnt[Gg];
__device__ int g_edgecnt[Gg];
__device__ int g_indeg[Nn];
__device__ int g_scantmp[Nn];
__device__ int g_bsum[64];
__device__ int g_bsumscan[64];
__device__ int g_rowstart[Nn+1];
__device__ int g_cursor[Nn];
__device__ int g_csr_src[Ee];

// ======================= warp MMA helpers (plain-target: sm_80+) =======================
__device__ __forceinline__ uint32_t smem_to_u32(const void* smem_ptr) {
    uint32_t addr;
    asm("{ .reg .u64 tmp; cvta.to.shared.u64 tmp, %1; cvt.u32.u64 %0, tmp; }"
        : "=r"(addr) : "l"(smem_ptr));
    return addr;
}
#define LDSM4(r0,r1,r2,r3,addr) \
    asm volatile("ldmatrix.sync.aligned.m8n8.x4.shared.b16 {%0,%1,%2,%3}, [%4];" \
        : "=r"(r0), "=r"(r1), "=r"(r2), "=r"(r3) : "r"(addr))
#define MMA16816(c, a, b) \
    asm volatile("mma.sync.aligned.m16n8k16.row.col.f32.bf16.bf16.f32 " \
        "{%0,%1,%2,%3}, {%4,%5,%6,%7}, {%8,%9}, {%0,%1,%2,%3};" \
        : "+f"((c)[0]), "+f"((c)[1]), "+f"((c)[2]), "+f"((c)[3]) \
        : "r"((a)[0]), "r"((a)[1]), "r"((a)[2]), "r"((a)[3]), \
          "r"((b)[0]), "r"((b)[1]))

// ---------------- small kernels ----------------
__global__ void k_zero() {
    int i = blockIdx.x*blockDim.x + threadIdx.x;
    if (i < Gg) { g_nodecnt[i]=0; g_edgecnt[i]=0; }
    if (i < Nn) g_indeg[i]=0;
}

__global__ void k_encoder(const float* __restrict__ x, const float* __restrict__ W,
                          const float* __restrict__ b) {
    int idx = blockIdx.x*blockDim.x + threadIdx.x;
    if (idx >= NH) return;
    int i = idx >> 8, c = idx & 255;
    float acc = b[c];
#pragma unroll
    for (int k=0;k<Ff;k++) acc += x[i*Ff+k]*W[k*Hh+c];
    float v = fmaxf(acc, 0.f);
    g_h[idx] = v;
    __nv_bfloat16 hi = __float2bfloat16(v);
    g_A0h[idx] = hi;
    g_A0l[idx] = __float2bfloat16(v - __bfloat162float(hi));
}

// convert + transpose all weights to bf16 hi/lo, layout [mat][n][k]
__global__ void k_convW(const float* __restrict__ rW1, const float* __restrict__ hWr,
                        const float* __restrict__ hWn) {
    size_t idx = (size_t)blockIdx.x*blockDim.x + threadIdx.x;
    if (idx >= (size_t)NMATS*65536) return;
    int mat = (int)(idx >> 16);
    int r = (int)(idx & 65535);
    int n = r >> 8, k = r & 255;
    float w;
    if (mat == 0) {
        w = rW1[k*256 + n];
    } else {
        int hm = mat - 1;
        int l = hm >> 4, rr = hm & 15;
        int e = rr >> 1, m = rr & 1;
        const float* W = m ? hWn : hWr;
        w = W[((size_t)(l*NEx + e))*65536 + k*256 + n];
    }
    __nv_bfloat16 hi = __float2bfloat16(w);
    g_Wth[idx] = hi;
    g_Wtl[idx] = __float2bfloat16(w - __bfloat162float(hi));
}

__global__ void k_count_nodes(const int* __restrict__ batch) {
    __shared__ int hist[Gg];
    int t = threadIdx.x;
    if (t < Gg) hist[t]=0;
    __syncthreads();
    for (int i = blockIdx.x*blockDim.x + t; i < Nn; i += gridDim.x*blockDim.x)
        atomicAdd(&hist[batch[i]], 1);
    __syncthreads();
    if (t < Gg) atomicAdd(&g_nodecnt[t], hist[t]);
}

__global__ void k_count_edges(const int* __restrict__ ei, const int* __restrict__ batch) {
    __shared__ int hist[Gg];
    int t = threadIdx.x;
    if (t < Gg) hist[t]=0;
    __syncthreads();
    for (int e = blockIdx.x*blockDim.x + t; e < Ee; e += gridDim.x*blockDim.x)
        atomicAdd(&hist[batch[ei[e]]], 1);
    __syncthreads();
    if (t < Gg) atomicAdd(&g_edgecnt[t], hist[t]);
}

__global__ void k_indeg(const int* __restrict__ ei) {
    int e = blockIdx.x*blockDim.x + threadIdx.x;
    if (e < Ee) atomicAdd(&g_indeg[ei[Ee+e]], 1);
}

__global__ void k_sizefeat(const int* __restrict__ batch) {
    int i = blockIdx.x*blockDim.x + threadIdx.x;
    if (i >= Nn) return;
    int g = batch[i];
    g_sf[i*2+0] = logf((float)g_nodecnt[g] + 1.f);
    g_sf[i*2+1] = logf((float)g_edgecnt[g] + 1.f);
}

__global__ void k_scan1() {
    __shared__ int sh[1024];
    int t = threadIdx.x, gid = blockIdx.x*1024 + t;
    sh[t] = (gid < Nn) ? g_indeg[gid] : 0;
    __syncthreads();
    for (int off=1; off<1024; off<<=1) {
        int a = (t>=off) ? sh[t-off] : 0;
        __syncthreads();
        sh[t] += a;
        __syncthreads();
    }
    if (gid < Nn) g_scantmp[gid] = sh[t];
    if (t == 1023) g_bsum[blockIdx.x] = sh[1023];
}

__global__ void k_scan2() {
    __shared__ int sh[64];
    int t = threadIdx.x;
    const int NB1 = (Nn + 1023)/1024;
    sh[t] = (t < NB1) ? g_bsum[t] : 0;
    __syncthreads();
    for (int off=1; off<64; off<<=1) {
        int a = (t>=off) ? sh[t-off] : 0;
        __syncthreads();
        sh[t] += a;
        __syncthreads();
    }
    g_bsumscan[t] = sh[t];
}

__global__ void k_scan3() {
    int i = blockIdx.x*blockDim.x + threadIdx.x;
    if (i >= Nn) return;
    int blk = i >> 10;
    int incl = g_scantmp[i] + (blk ? g_bsumscan[blk-1] : 0);
    g_rowstart[i+1] = incl;
    if (i == 0) g_rowstart[0] = 0;
}

__global__ void k_cursor() {
    int i = blockIdx.x*blockDim.x + threadIdx.x;
    if (i < Nn) g_cursor[i] = g_rowstart[i];
}

__global__ void k_scatter(const int* __restrict__ ei) {
    int e = blockIdx.x*blockDim.x + threadIdx.x;
    if (e >= Ee) return;
    int d = ei[Ee+e];
    int p = atomicAdd(&g_cursor[d], 1);
    g_csr_src[p] = ei[e];
}

// ---------------- router SGEMM (exact fp32, tile 128x128) ----------------
__global__ void __launch_bounds__(256) k_sgemm_router(const float* __restrict__ B) {
    const float* A = g_h;
    float* Cb = g_t;

    __shared__ float As[16][128];
    __shared__ float Bs[16][128];

    int tid = threadIdx.x;
    int bm = blockIdx.x*128, bn = blockIdx.y*128;
    int tx = tid & 15, ty = tid >> 4;
    int a_row = tid >> 2;
    int a_col = (tid & 3) * 4;
    int b_row = tid >> 5;
    int b_col = (tid & 31) * 4;

    float acc[8][8];
#pragma unroll
    for (int i=0;i<8;i++)
#pragma unroll
        for (int j=0;j<8;j++) acc[i][j]=0.f;

    for (int kt=0; kt<256; kt+=16) {
        __syncthreads();
#pragma unroll
        for (int i=0;i<2;i++) {
            int r = a_row + i*64;
            int gm = bm + r;
            float4 av = make_float4(0.f,0.f,0.f,0.f);
            if (gm < Nn) av = *(const float4*)(A + (size_t)gm*256 + kt + a_col);
            As[a_col+0][r]=av.x; As[a_col+1][r]=av.y;
            As[a_col+2][r]=av.z; As[a_col+3][r]=av.w;
        }
#pragma unroll
        for (int i=0;i<2;i++) {
            int r = b_row + i*8;
            *(float4*)&Bs[r][b_col] = *(const float4*)(B + (size_t)(kt+r)*256 + bn + b_col);
        }
        __syncthreads();
#pragma unroll
        for (int kk=0;kk<16;kk++) {
            float4 a0 = *(const float4*)&As[kk][ty*4];
            float4 a1 = *(const float4*)&As[kk][64+ty*4];
            float4 b0 = *(const float4*)&Bs[kk][tx*4];
            float4 b1 = *(const float4*)&Bs[kk][64+tx*4];
            float a[8] = {a0.x,a0.y,a0.z,a0.w,a1.x,a1.y,a1.z,a1.w};
            float b[8] = {b0.x,b0.y,b0.z,b0.w,b1.x,b1.y,b1.z,b1.w};
#pragma unroll
            for (int i=0;i<8;i++)
#pragma unroll
                for (int j=0;j<8;j++) acc[i][j] += a[i]*b[j];
        }
    }
#pragma unroll
    for (int ih=0; ih<2; ih++) {
#pragma unroll
        for (int i=0;i<4;i++) {
            int gm = bm + ih*64 + ty*4 + i;
            if (gm >= Nn) continue;
            float* crow = Cb + (size_t)gm*256 + bn;
            int r = ih*4 + i;
            *(float4*)(crow + tx*4)      = make_float4(acc[r][0],acc[r][1],acc[r][2],acc[r][3]);
            *(float4*)(crow + 64 + tx*4) = make_float4(acc[r][4],acc[r][5],acc[r][6],acc[r][7]);
        }
    }
}

// ============== HMMA bf16x3 GEMM =====================
// All device arrays referenced INSIDE the kernel (device symbols must never be
// passed as kernel arguments from host code — that was the rel_err=1.0 bug).
// C tile (128x128) of g_t/g_v[e] = A(e)[M,256] @ W(mat)[256,256], 3-term hi/lo split.
// BM=128, BN=128, BK=16, single-buffered, 8 warps (4x2), warp tile 32x64.
__global__ void k_hgemm(int layer0, int matBase)
{
    __shared__ __align__(16) __nv_bfloat16 sA[2][128][24];   // [hi/lo][row][k] pitch 24
    __shared__ __align__(16) __nv_bfloat16 sB[2][128][24];

    int tid = threadIdx.x, lane = tid & 31, wid = tid >> 5;
    int bm = blockIdx.x * 128, bn = blockIdx.y * 128;
    int z = blockIdx.z;                 // z = e*2 + m
    int e = z >> 1, m = z & 1;
    int mat = matBase + z;

    const __nv_bfloat16* Abh = layer0 ? g_A0h : (g_Ah + (size_t)e * NH);
    const __nv_bfloat16* Abl = layer0 ? g_A0l : (g_Al + (size_t)e * NH);
    const __nv_bfloat16* Bh = g_Wth + (size_t)mat * 65536;
    const __nv_bfloat16* Bl = g_Wtl + (size_t)mat * 65536;

    int wm = (wid & 3) * 32;
    int wn = (wid >> 2) * 64;

    float c[2][8][4];
#pragma unroll
    for (int mi=0;mi<2;mi++)
#pragma unroll
        for (int nf=0;nf<8;nf++)
#pragma unroll
            for (int r=0;r<4;r++) c[mi][nf][r] = 0.f;

    // per-thread load slot: 256 threads cover 128 rows x 2 chunks (8 bf16 each)
    int lrow = tid >> 1, lch = tid & 1;
    int agr = bm + lrow;
    bool aok = (agr < Nn);
    const uint4 zero4 = make_uint4(0,0,0,0);

    uint32_t sA0 = smem_to_u32(&sA[0][0][0]);
    uint32_t sA1 = smem_to_u32(&sA[1][0][0]);
    uint32_t sB0 = smem_to_u32(&sB[0][0][0]);
    uint32_t sB1 = smem_to_u32(&sB[1][0][0]);

    int rsel = lane & 15;                         // ldmatrix row-within-16
    int cofs = (lane & 16) ? 16 : 0;              // byte offset: k 8-15 half

    for (int kt = 0; kt < 16; kt++) {
        int k0 = kt * 16;
        // hoisted global loads (overlap with previous iteration's MMAs)
        uint4 vh = aok ? *(const uint4*)(Abh + (size_t)agr*256 + k0 + lch*8) : zero4;
        uint4 vl = aok ? *(const uint4*)(Abl + (size_t)agr*256 + k0 + lch*8) : zero4;
        uint4 wh = *(const uint4*)(Bh + (size_t)(bn + lrow)*256 + k0 + lch*8);
        uint4 wl = *(const uint4*)(Bl + (size_t)(bn + lrow)*256 + k0 + lch*8);
        __syncthreads();   // previous compute done before overwriting smem
        *(uint4*)&sA[0][lrow][lch*8] = vh;
        *(uint4*)&sA[1][lrow][lch*8] = vl;
        *(uint4*)&sB[0][lrow][lch*8] = wh;
        *(uint4*)&sB[1][lrow][lch*8] = wl;
        __syncthreads();

        uint32_t a_h[2][4], a_l[2][4];
#pragma unroll
        for (int mi = 0; mi < 2; mi++) {
            uint32_t ro = (uint32_t)(wm + mi*16 + rsel) * 48 + cofs;
            LDSM4(a_h[mi][0], a_h[mi][1], a_h[mi][2], a_h[mi][3], sA0 + ro);
            LDSM4(a_l[mi][0], a_l[mi][1], a_l[mi][2], a_l[mi][3], sA1 + ro);
        }
        uint32_t b_h[8][2], b_l[8][2];
#pragma unroll
        for (int np = 0; np < 4; np++) {
            uint32_t ro = (uint32_t)(wn + np*16 + rsel) * 48 + cofs;
            uint32_t r0, r1, r2, r3;
            LDSM4(r0, r1, r2, r3, sB0 + ro);
            b_h[np*2][0]=r0; b_h[np*2+1][0]=r1; b_h[np*2][1]=r2; b_h[np*2+1][1]=r3;
            LDSM4(r0, r1, r2, r3, sB1 + ro);
            b_l[np*2][0]=r0; b_l[np*2+1][0]=r1; b_l[np*2][1]=r2; b_l[np*2+1][1]=r3;
        }
#pragma unroll
        for (int mi = 0; mi < 2; mi++)
#pragma unroll
            for (int nf = 0; nf < 8; nf++) {
                MMA16816(c[mi][nf], a_h[mi], b_h[nf]);
                MMA16816(c[mi][nf], a_h[mi], b_l[nf]);
                MMA16816(c[mi][nf], a_l[mi], b_h[nf]);
            }
    }

    // epilogue (g_t / g_v referenced as device globals)
    float* C = (m ? g_v : g_t) + (size_t)e * NH;
#pragma unroll
    for (int mi = 0; mi < 2; mi++) {
        int row0 = bm + wm + mi*16 + (lane >> 2);
#pragma unroll
        for (int nf = 0; nf < 8; nf++) {
            int col = bn + wn + nf*8 + (lane & 3)*2;
            if (row0 < Nn)
                *(float2*)(C + (size_t)row0*256 + col) = make_float2(c[mi][nf][0], c[mi][nf][1]);
            if (row0 + 8 < Nn)
                *(float2*)(C + (size_t)(row0+8)*256 + col) = make_float2(c[mi][nf][2], c[mi][nf][3]);
        }
    }
}

// ---------------- router epilogue ----------------
__global__ void k_router_epi(const float* __restrict__ W1, const float* __restrict__ b1) {
    int idx = blockIdx.x*blockDim.x + threadIdx.x;
    if (idx >= NH) return;
    int i = idx >> 8, c = idx & 255;
    float v = g_t[idx] + g_sf[i*2]*W1[256*256+c] + g_sf[i*2+1]*W1[257*256+c] + b1[c];
    g_r[idx] = fmaxf(v, 0.f);
}

__global__ void k_logits(const float* __restrict__ W2, const float* __restrict__ b2) {
    int idx = blockIdx.x*blockDim.x + threadIdx.x;
    if (idx >= Nn*NEx) return;
    int i = idx >> 3, e2 = idx & 7;
    const float* r = g_r + (size_t)i*256;
    float acc = b2[e2];
#pragma unroll 8
    for (int k=0;k<256;k++) acc += r[k]*W2[k*8+e2];
    g_logits[idx] = acc;
}

__global__ void k_topk() {
    int i = blockIdx.x*blockDim.x + threadIdx.x;
    if (i >= Nn) return;
    float l[8];
#pragma unroll
    for (int e=0;e<8;e++) l[e] = g_logits[i*8+e];
    int i1 = 0; float m1 = l[0];
#pragma unroll
    for (int e=1;e<8;e++) if (l[e] > m1) { m1 = l[e]; i1 = e; }
    int i2 = -1; float m2 = -1e30f;
#pragma unroll
    for (int e=0;e<8;e++) if (e != i1 && l[e] > m2) { m2 = l[e]; i2 = e; }
    float e2v = expf(m2 - m1);
    float inv = 1.f/(1.f + e2v);
    float s[8];
#pragma unroll
    for (int e=0;e<8;e++) s[e]=0.f;
    s[i1] = inv; s[i2] = e2v*inv;
#pragma unroll
    for (int e=0;e<8;e++) g_sparse[i*8+e] = s[e];
}

// ---------------- SpMM + combine + bf16 split, fused ----------------
__global__ void k_spmm_combine(const float* __restrict__ bias) {
    int dst = blockIdx.x;
    int e = blockIdx.y;
    int t = threadIdx.x;
    const float* vb = g_v + (size_t)e*NH;
    int s0 = g_rowstart[dst], s1 = g_rowstart[dst+1];
    __shared__ int ssrc[256];
    float acc = 0.f;
    for (int base = s0; base < s1; base += 256) {
        int cnt = min(256, s1 - base);
        __syncthreads();
        if (t < cnt) ssrc[t] = g_csr_src[base + t];
        __syncthreads();
#pragma unroll 4
        for (int k=0;k<cnt;k++) acc += vb[(size_t)ssrc[k]*256 + t];
    }
    size_t idx = (size_t)e*NH + (size_t)dst*256 + t;
    float val = fmaxf(g_t[idx] + acc + bias[e*256 + t], 0.f);
    __nv_bfloat16 hi = __float2bfloat16(val);
    g_Ah[idx] = hi;
    g_Al[idx] = __float2bfloat16(val - __bfloat162float(hi));
}

// ---------------- output layer: one thread per (e,i), computes m0,m1,z0,z1 ----------------
__global__ void k_mz(const float* __restrict__ Wr, const float* __restrict__ Wn) {
    int idx = blockIdx.x*blockDim.x + threadIdx.x;
    if (idx >= NEx*Nn) return;
    int i = idx % Nn, e = idx / Nn;
    const uint4* ah = (const uint4*)(g_Ah + (size_t)e*NH + (size_t)i*256);
    const uint4* al = (const uint4*)(g_Al + (size_t)e*NH + (size_t)i*256);
    const float* WRe = Wr + e*512;
    const float* WNe = Wn + e*512;
    float m0=0.f, m1=0.f, z0=0.f, z1=0.f;
#pragma unroll 4
    for (int k8 = 0; k8 < 32; k8++) {
        uint4 vh = ah[k8], vl = al[k8];
        const __nv_bfloat16* ph = (const __nv_bfloat16*)&vh;
        const __nv_bfloat16* pl = (const __nv_bfloat16*)&vl;
#pragma unroll
        for (int j = 0; j < 8; j++) {
            float a = __bfloat162float(ph[j]) + __bfloat162float(pl[j]);
            int k = k8*8 + j;
            m0 += a*WRe[k*2];   m1 += a*WRe[k*2+1];
            z0 += a*WNe[k*2];   z1 += a*WNe[k*2+1];
        }
    }
    float* o = g_mz + (size_t)idx*4;
    o[0]=m0; o[1]=m1; o[2]=z0; o[3]=z1;
}

__global__ void k_aggz() {
    int idx = blockIdx.x*blockDim.x + threadIdx.x;
    if (idx >= NEx*Nn) return;
    int dst = idx % Nn;
    int e = idx / Nn;
    int s0 = g_rowstart[dst], s1 = g_rowstart[dst+1];
    float a0=0.f, a1=0.f;
    for (int p=s0; p<s1; p++) {
        int src = g_csr_src[p];
        const float* z = g_mz + ((size_t)e*Nn + src)*4 + 2;
        a0 += z[0]; a1 += z[1];
    }
    g_aggz[((size_t)e*Nn+dst)*2+0] = a0;
    g_aggz[((size_t)e*Nn+dst)*2+1] = a1;
}

__global__ void k_final(const float* __restrict__ outb, float* __restrict__ out) {
    int i = blockIdx.x*blockDim.x + threadIdx.x;
    if (i >= Nn) return;
    float o0=0.f, o1=0.f;
#pragma unroll
    for (int e=0;e<8;e++) {
        float s = g_sparse[i*8+e];
        const float* mz = g_mz + ((size_t)e*Nn+i)*4;
        const float* az = g_aggz + ((size_t)e*Nn+i)*2;
        o0 += s*(mz[0] + az[0] + outb[e*2+0]);
        o1 += s*(mz[1] + az[1] + outb[e*2+1]);
    }
    out[i*2+0] = o0;
    out[i*2+1] = o1;
}

// ---------------- launch ----------------
extern "C" void kernel_launch(void* const* d_in, const int* in_sizes, int n_in,
                              void* d_out, int out_size) {
    const float* x    = (const float*)d_in[0];
    const int*   ei   = (const int*)  d_in[1];
    const int*   batch= (const int*)  d_in[2];
    const float* encW = (const float*)d_in[3];
    const float* encb = (const float*)d_in[4];
    const float* rW1  = (const float*)d_in[5];
    const float* rb1  = (const float*)d_in[6];
    const float* rW2  = (const float*)d_in[7];
    const float* rb2  = (const float*)d_in[8];
    const float* hWr  = (const float*)d_in[9];
    const float* hWn  = (const float*)d_in[10];
    const float* hb   = (const float*)d_in[11];
    const float* oWr  = (const float*)d_in[12];
    const float* oWn  = (const float*)d_in[13];
    const float* ob   = (const float*)d_in[14];
    float* out = (float*)d_out;

    k_zero<<<(Nn+255)/256,256>>>();
    k_encoder<<<(NH+255)/256,256>>>(x, encW, encb);
    k_convW<<<(NMATS*65536+255)/256,256>>>(rW1, hWr, hWn);
    k_count_nodes<<<256,256>>>(batch);
    k_count_edges<<<512,256>>>(ei, batch);
    k_indeg<<<(Ee+255)/256,256>>>(ei);
    k_sizefeat<<<(Nn+255)/256,256>>>(batch);
    k_scan1<<<(Nn+1023)/1024,1024>>>();
    k_scan2<<<1,64>>>();
    k_scan3<<<(Nn+255)/256,256>>>();
    k_cursor<<<(Nn+255)/256,256>>>();
    k_scatter<<<(Ee+255)/256,256>>>(ei);

    // router (exact fp32 to keep top-k selection bit-stable)
    {
        dim3 gR((Nn+127)/128, 2, 1);
        k_sgemm_router<<<gR,256>>>(rW1);
        k_router_epi<<<(NH+255)/256,256>>>(rW1, rb1);
        k_logits<<<(Nn*NEx+255)/256,256>>>(rW2, rb2);
        k_topk<<<(Nn+255)/256,256>>>();
    }

    // hidden layers: HMMA bf16x3 GEMMs + fused SpMM/combine
    const int NTILES = (Nn + 127) / 128;   // 391
    dim3 gG(NTILES, 2, NEx*2);             // (mtile, ntile, e*2+mat)
    dim3 gS(Nn, NEx, 1);
    for (int l = 0; l < 3; l++) {
        int matBase = 1 + l*(NEx*2);
        k_hgemm<<<gG,256>>>(l == 0 ? 1 : 0, matBase);
        k_spmm_combine<<<gS,256>>>(hb + (size_t)l*NEx*Hh);
    }

    // output layer
    k_mz<<<(NEx*Nn+255)/256,256>>>(oWr, oWn);
    k_aggz<<<(NEx*Nn+255)/256,256>>>();
    k_final<<<(Nn+255)/256,256>>>(ob, out);
}

// round 7
// speedup vs baseline: 2.2144x; 1.0392x over previous
#include <cuda_runtime.h>
#include <cuda_bf16.h>
#include <cstdint>
#include <math.h>

#define Nn 50000
#define Ee 800000
#define Gg 64
#define Ff 6
#define Hh 256
#define Oo 2
#define NEx 8
#define NH (Nn*Hh)
#define NMATS 49   // 1 router + 3 layers * 8 experts * 2

// ---------------- scratch (static __device__ arrays; no allocation) ----------------
__device__ __align__(128) float g_h[NH];                  // encoder output (fp32, router uses it)
__device__ __align__(128) __nv_bfloat16 g_A0h[NH];        // encoder bf16 hi
__device__ __align__(128) __nv_bfloat16 g_A0l[NH];        // encoder bf16 lo
__device__ __align__(128) float g_r[NH];                  // router hidden
__device__ __align__(128) float g_rt[NH];                 // router GEMM scratch (own buffer)
__device__ __align__(128) float g_t[NEx*NH];              // he @ Wr
__device__ __align__(128) float g_v[NEx*NH];              // he @ Wn
__device__ __align__(128) __nv_bfloat16 g_Ah[NEx*NH];     // per-expert activation bf16 hi
__device__ __align__(128) __nv_bfloat16 g_Al[NEx*NH];     // per-expert activation bf16 lo
__device__ __align__(128) __nv_bfloat16 g_Wth[NMATS*65536]; // transposed weights bf16 hi  [mat][n][k]
__device__ __align__(128) __nv_bfloat16 g_Wtl[NMATS*65536]; // transposed weights bf16 lo
__device__ __align__(128) float g_sf[Nn*2];
__device__ __align__(128) float g_logits[Nn*NEx];
__device__ __align__(128) float g_sparse[Nn*NEx];
__device__ __align__(128) float g_mz[NEx*Nn*4];           // [m0,m1,z0,z1] per (e,node)
__device__ __align__(128) float g_aggz[NEx*Nn*2];
__device__ int g_nodecnt[Gg];
__device__ int g_edgecnt[Gg];
__device__ int g_indeg[Nn];
__device__ int g_scantmp[Nn];
__device__ int g_bsum[64];
__device__ int g_bsumscan[64];
__device__ int g_rowstart[Nn+1];
__device__ int g_cursor[Nn];
__device__ int g_csr_src[Ee];

// ======================= warp MMA helpers (plain-target: sm_80+) =======================
__device__ __forceinline__ uint32_t smem_to_u32(const void* smem_ptr) {
    uint32_t addr;
    asm("{ .reg .u64 tmp; cvta.to.shared.u64 tmp, %1; cvt.u32.u64 %0, tmp; }"
        : "=r"(addr) : "l"(smem_ptr));
    return addr;
}
#define LDSM4(r0,r1,r2,r3,addr) \
    asm volatile("ldmatrix.sync.aligned.m8n8.x4.shared.b16 {%0,%1,%2,%3}, [%4];" \
        : "=r"(r0), "=r"(r1), "=r"(r2), "=r"(r3) : "r"(addr))
#define MMA16816(c, a, b) \
    asm volatile("mma.sync.aligned.m16n8k16.row.col.f32.bf16.bf16.f32 " \
        "{%0,%1,%2,%3}, {%4,%5,%6,%7}, {%8,%9}, {%0,%1,%2,%3};" \
        : "+f"((c)[0]), "+f"((c)[1]), "+f"((c)[2]), "+f"((c)[3]) \
        : "r"((a)[0]), "r"((a)[1]), "r"((a)[2]), "r"((a)[3]), \
          "r"((b)[0]), "r"((b)[1]))
#define CPA16(dst, src) \
    asm volatile("cp.async.cg.shared.global [%0], [%1], 16;" :: "r"(dst), "l"(src))
#define CP_COMMIT() asm volatile("cp.async.commit_group;")
#define CP_WAIT1()  asm volatile("cp.async.wait_group 1;")
#define CP_WAIT0()  asm volatile("cp.async.wait_group 0;")

// ---------------- small kernels ----------------
__global__ void k_zero() {
    int i = blockIdx.x*blockDim.x + threadIdx.x;
    if (i < Gg) { g_nodecnt[i]=0; g_edgecnt[i]=0; }
    if (i < Nn) g_indeg[i]=0;
}

__global__ void k_encoder(const float* __restrict__ x, const float* __restrict__ W,
                          const float* __restrict__ b) {
    int idx = blockIdx.x*blockDim.x + threadIdx.x;
    if (idx >= NH) return;
    int i = idx >> 8, c = idx & 255;
    float acc = b[c];
#pragma unroll
    for (int k=0;k<Ff;k++) acc += x[i*Ff+k]*W[k*Hh+c];
    float v = fmaxf(acc, 0.f);
    g_h[idx] = v;
    __nv_bfloat16 hi = __float2bfloat16(v);
    g_A0h[idx] = hi;
    g_A0l[idx] = __float2bfloat16(v - __bfloat162float(hi));
}

// convert + transpose all weights to bf16 hi/lo, layout [mat][n][k]
__global__ void k_convW(const float* __restrict__ rW1, const float* __restrict__ hWr,
                        const float* __restrict__ hWn) {
    size_t idx = (size_t)blockIdx.x*blockDim.x + threadIdx.x;
    if (idx >= (size_t)NMATS*65536) return;
    int mat = (int)(idx >> 16);
    int r = (int)(idx & 65535);
    int n = r >> 8, k = r & 255;
    float w;
    if (mat == 0) {
        w = rW1[k*256 + n];
    } else {
        int hm = mat - 1;
        int l = hm >> 4, rr = hm & 15;
        int e = rr >> 1, m = rr & 1;
        const float* W = m ? hWn : hWr;
        w = W[((size_t)(l*NEx + e))*65536 + k*256 + n];
    }
    __nv_bfloat16 hi = __float2bfloat16(w);
    g_Wth[idx] = hi;
    g_Wtl[idx] = __float2bfloat16(w - __bfloat162float(hi));
}

__global__ void k_count_nodes(const int* __restrict__ batch) {
    __shared__ int hist[Gg];
    int t = threadIdx.x;
    if (t < Gg) hist[t]=0;
    __syncthreads();
    for (int i = blockIdx.x*blockDim.x + t; i < Nn; i += gridDim.x*blockDim.x)
        atomicAdd(&hist[batch[i]], 1);
    __syncthreads();
    if (t < Gg) atomicAdd(&g_nodecnt[t], hist[t]);
}

__global__ void k_count_edges(const int* __restrict__ ei, const int* __restrict__ batch) {
    __shared__ int hist[Gg];
    int t = threadIdx.x;
    if (t < Gg) hist[t]=0;
    __syncthreads();
    for (int e = blockIdx.x*blockDim.x + t; e < Ee; e += gridDim.x*blockDim.x)
        atomicAdd(&hist[batch[ei[e]]], 1);
    __syncthreads();
    if (t < Gg) atomicAdd(&g_edgecnt[t], hist[t]);
}

__global__ void k_indeg(const int* __restrict__ ei) {
    int e = blockIdx.x*blockDim.x + threadIdx.x;
    if (e < Ee) atomicAdd(&g_indeg[ei[Ee+e]], 1);
}

__global__ void k_sizefeat(const int* __restrict__ batch) {
    int i = blockIdx.x*blockDim.x + threadIdx.x;
    if (i >= Nn) return;
    int g = batch[i];
    g_sf[i*2+0] = logf((float)g_nodecnt[g] + 1.f);
    g_sf[i*2+1] = logf((float)g_edgecnt[g] + 1.f);
}

__global__ void k_scan1() {
    __shared__ int sh[1024];
    int t = threadIdx.x, gid = blockIdx.x*1024 + t;
    sh[t] = (gid < Nn) ? g_indeg[gid] : 0;
    __syncthreads();
    for (int off=1; off<1024; off<<=1) {
        int a = (t>=off) ? sh[t-off] : 0;
        __syncthreads();
        sh[t] += a;
        __syncthreads();
    }
    if (gid < Nn) g_scantmp[gid] = sh[t];
    if (t == 1023) g_bsum[blockIdx.x] = sh[1023];
}

__global__ void k_scan2() {
    __shared__ int sh[64];
    int t = threadIdx.x;
    const int NB1 = (Nn + 1023)/1024;
    sh[t] = (t < NB1) ? g_bsum[t] : 0;
    __syncthreads();
    for (int off=1; off<64; off<<=1) {
        int a = (t>=off) ? sh[t-off] : 0;
        __syncthreads();
        sh[t] += a;
        __syncthreads();
    }
    g_bsumscan[t] = sh[t];
}

__global__ void k_scan3() {
    int i = blockIdx.x*blockDim.x + threadIdx.x;
    if (i >= Nn) return;
    int blk = i >> 10;
    int incl = g_scantmp[i] + (blk ? g_bsumscan[blk-1] : 0);
    g_rowstart[i+1] = incl;
    if (i == 0) g_rowstart[0] = 0;
}

__global__ void k_cursor() {
    int i = blockIdx.x*blockDim.x + threadIdx.x;
    if (i < Nn) g_cursor[i] = g_rowstart[i];
}

__global__ void k_scatter(const int* __restrict__ ei) {
    int e = blockIdx.x*blockDim.x + threadIdx.x;
    if (e >= Ee) return;
    int d = ei[Ee+e];
    int p = atomicAdd(&g_cursor[d], 1);
    g_csr_src[p] = ei[e];
}

// ---------------- router SGEMM (exact fp32, tile 128x128) -> g_rt ----------------
__global__ void __launch_bounds__(256) k_sgemm_router(const float* __restrict__ B) {
    const float* A = g_h;
    float* Cb = g_rt;

    __shared__ float As[16][128];
    __shared__ float Bs[16][128];

    int tid = threadIdx.x;
    int bm = blockIdx.x*128, bn = blockIdx.y*128;
    int tx = tid & 15, ty = tid >> 4;
    int a_row = tid >> 2;
    int a_col = (tid & 3) * 4;
    int b_row = tid >> 5;
    int b_col = (tid & 31) * 4;

    float acc[8][8];
#pragma unroll
    for (int i=0;i<8;i++)
#pragma unroll
        for (int j=0;j<8;j++) acc[i][j]=0.f;

    for (int kt=0; kt<256; kt+=16) {
        __syncthreads();
#pragma unroll
        for (int i=0;i<2;i++) {
            int r = a_row + i*64;
            int gm = bm + r;
            float4 av = make_float4(0.f,0.f,0.f,0.f);
            if (gm < Nn) av = *(const float4*)(A + (size_t)gm*256 + kt + a_col);
            As[a_col+0][r]=av.x; As[a_col+1][r]=av.y;
            As[a_col+2][r]=av.z; As[a_col+3][r]=av.w;
        }
#pragma unroll
        for (int i=0;i<2;i++) {
            int r = b_row + i*8;
            *(float4*)&Bs[r][b_col] = *(const float4*)(B + (size_t)(kt+r)*256 + bn + b_col);
        }
        __syncthreads();
#pragma unroll
        for (int kk=0;kk<16;kk++) {
            float4 a0 = *(const float4*)&As[kk][ty*4];
            float4 a1 = *(const float4*)&As[kk][64+ty*4];
            float4 b0 = *(const float4*)&Bs[kk][tx*4];
            float4 b1 = *(const float4*)&Bs[kk][64+tx*4];
            float a[8] = {a0.x,a0.y,a0.z,a0.w,a1.x,a1.y,a1.z,a1.w};
            float b[8] = {b0.x,b0.y,b0.z,b0.w,b1.x,b1.y,b1.z,b1.w};
#pragma unroll
            for (int i=0;i<8;i++)
#pragma unroll
                for (int j=0;j<8;j++) acc[i][j] += a[i]*b[j];
        }
    }
#pragma unroll
    for (int ih=0; ih<2; ih++) {
#pragma unroll
        for (int i=0;i<4;i++) {
            int gm = bm + ih*64 + ty*4 + i;
            if (gm >= Nn) continue;
            float* crow = Cb + (size_t)gm*256 + bn;
            int r = ih*4 + i;
            *(float4*)(crow + tx*4)      = make_float4(acc[r][0],acc[r][1],acc[r][2],acc[r][3]);
            *(float4*)(crow + 64 + tx*4) = make_float4(acc[r][4],acc[r][5],acc[r][6],acc[r][7]);
        }
    }
}

// ============== HMMA bf16x3 GEMM, cp.async 2-stage pipeline =====================
// C tile (128x128) of g_t/g_v[e] = A(e)[M,256] @ W(mat)[256,256], 3-term hi/lo split.
// BM=128, BN=128, BK=16. 8 warps (4x2), warp tile 32x64.
// Stage layout (24576B): Ah @0, Al @6144, Bh @12288, Bl @18432 — rows pitch 48B.
// Two stages = 49152B static shared.
#define HG_STAGE 24576

__global__ void __launch_bounds__(256) k_hgemm(int layer0, int matBase)
{
    __shared__ __align__(16) char smarr[2*HG_STAGE];
    uint32_t sbase = smem_to_u32(smarr);
    int tid = threadIdx.x, lane = tid & 31, wid = tid >> 5;
    int bm = blockIdx.x * 128, bn = blockIdx.y * 128;
    int z = blockIdx.z;                 // z = e*2 + m
    int e = z >> 1, m = z & 1;
    int mat = matBase + z;

    const __nv_bfloat16* Abh = layer0 ? g_A0h : (g_Ah + (size_t)e * NH);
    const __nv_bfloat16* Abl = layer0 ? g_A0l : (g_Al + (size_t)e * NH);
    const __nv_bfloat16* Bh = g_Wth + (size_t)mat * 65536;
    const __nv_bfloat16* Bl = g_Wtl + (size_t)mat * 65536;

    int wm = (wid & 3) * 32;
    int wn = (wid >> 2) * 64;

    float c[2][8][4];
#pragma unroll
    for (int mi=0;mi<2;mi++)
#pragma unroll
        for (int nf=0;nf<8;nf++)
#pragma unroll
            for (int r=0;r<4;r++) c[mi][nf][r] = 0.f;

    // cp.async slots: each thread loads one 16B chunk into each of the 4 arrays.
    int lrow = tid >> 1, lch = tid & 1;
    int agr = bm + lrow; if (agr >= Nn) agr = Nn - 1;   // clamp: junk rows masked on store
    const __nv_bfloat16* srcAh = Abh + (size_t)agr*256 + lch*8;
    const __nv_bfloat16* srcAl = Abl + (size_t)agr*256 + lch*8;
    const __nv_bfloat16* srcBh = Bh + (size_t)(bn + lrow)*256 + lch*8;
    const __nv_bfloat16* srcBl = Bl + (size_t)(bn + lrow)*256 + lch*8;
    uint32_t dstOff = (uint32_t)lrow*48 + (uint32_t)lch*16;

    // prologue: stage 0 covers k [0,16)
    {
        uint32_t d = sbase + dstOff;
        CPA16(d,         srcAh);
        CPA16(d + 6144,  srcAl);
        CPA16(d + 12288, srcBh);
        CPA16(d + 18432, srcBl);
        CP_COMMIT();
    }

    int rsel = lane & 15;                         // ldmatrix row-within-16
    int cofs = (lane & 16) ? 16 : 0;              // byte offset: k 8-15 half

    for (int kt = 0; kt < 16; kt++) {
        if (kt < 15) {
            int k0 = (kt + 1) * 16;
            uint32_t d = sbase + ((kt + 1) & 1) * HG_STAGE + dstOff;
            CPA16(d,         srcAh + k0);
            CPA16(d + 6144,  srcAl + k0);
            CPA16(d + 12288, srcBh + k0);
            CPA16(d + 18432, srcBl + k0);
            CP_COMMIT();
            CP_WAIT1();
        } else {
            CP_WAIT0();
        }
        __syncthreads();
        uint32_t buf = sbase + (kt & 1) * HG_STAGE;

        uint32_t a_h[2][4], a_l[2][4];
#pragma unroll
        for (int mi = 0; mi < 2; mi++) {
            uint32_t ro = buf + (uint32_t)(wm + mi*16 + rsel) * 48 + cofs;
            LDSM4(a_h[mi][0], a_h[mi][1], a_h[mi][2], a_h[mi][3], ro);
            LDSM4(a_l[mi][0], a_l[mi][1], a_l[mi][2], a_l[mi][3], ro + 6144);
        }
        uint32_t b_h[8][2], b_l[8][2];
#pragma unroll
        for (int np = 0; np < 4; np++) {
            uint32_t ro = buf + 12288 + (uint32_t)(wn + np*16 + rsel) * 48 + cofs;
            uint32_t r0, r1, r2, r3;
            LDSM4(r0, r1, r2, r3, ro);
            b_h[np*2][0]=r0; b_h[np*2+1][0]=r1; b_h[np*2][1]=r2; b_h[np*2+1][1]=r3;
            LDSM4(r0, r1, r2, r3, ro + 6144);
            b_l[np*2][0]=r0; b_l[np*2+1][0]=r1; b_l[np*2][1]=r2; b_l[np*2+1][1]=r3;
        }
#pragma unroll
        for (int mi = 0; mi < 2; mi++)
#pragma unroll
            for (int nf = 0; nf < 8; nf++) {
                MMA16816(c[mi][nf], a_h[mi], b_h[nf]);
                MMA16816(c[mi][nf], a_h[mi], b_l[nf]);
                MMA16816(c[mi][nf], a_l[mi], b_h[nf]);
            }
        __syncthreads();
    }

    // epilogue (g_t / g_v referenced as device globals)
    float* C = (m ? g_v : g_t) + (size_t)e * NH;
#pragma unroll
    for (int mi = 0; mi < 2; mi++) {
        int row0 = bm + wm + mi*16 + (lane >> 2);
#pragma unroll
        for (int nf = 0; nf < 8; nf++) {
            int col = bn + wn + nf*8 + (lane & 3)*2;
            if (row0 < Nn)
                *(float2*)(C + (size_t)row0*256 + col) = make_float2(c[mi][nf][0], c[mi][nf][1]);
            if (row0 + 8 < Nn)
                *(float2*)(C + (size_t)(row0+8)*256 + col) = make_float2(c[mi][nf][2], c[mi][nf][3]);
        }
    }
}

// ---------------- router epilogue ----------------
__global__ void k_router_epi(const float* __restrict__ W1, const float* __restrict__ b1) {
    int idx = blockIdx.x*blockDim.x + threadIdx.x;
    if (idx >= NH) return;
    int i = idx >> 8, c = idx & 255;
    float v = g_rt[idx] + g_sf[i*2]*W1[256*256+c] + g_sf[i*2+1]*W1[257*256+c] + b1[c];
    g_r[idx] = fmaxf(v, 0.f);
}

__global__ void k_logits(const float* __restrict__ W2, const float* __restrict__ b2) {
    int idx = blockIdx.x*blockDim.x + threadIdx.x;
    if (idx >= Nn*NEx) return;
    int i = idx >> 3, e2 = idx & 7;
    const float* r = g_r + (size_t)i*256;
    float acc = b2[e2];
#pragma unroll 8
    for (int k=0;k<256;k++) acc += r[k]*W2[k*8+e2];
    g_logits[idx] = acc;
}

__global__ void k_topk() {
    int i = blockIdx.x*blockDim.x + threadIdx.x;
    if (i >= Nn) return;
    float l[8];
#pragma unroll
    for (int e=0;e<8;e++) l[e] = g_logits[i*8+e];
    int i1 = 0; float m1 = l[0];
#pragma unroll
    for (int e=1;e<8;e++) if (l[e] > m1) { m1 = l[e]; i1 = e; }
    int i2 = -1; float m2 = -1e30f;
#pragma unroll
    for (int e=0;e<8;e++) if (e != i1 && l[e] > m2) { m2 = l[e]; i2 = e; }
    float e2v = expf(m2 - m1);
    float inv = 1.f/(1.f + e2v);
    float s[8];
#pragma unroll
    for (int e=0;e<8;e++) s[e]=0.f;
    s[i1] = inv; s[i2] = e2v*inv;
#pragma unroll
    for (int e=0;e<8;e++) g_sparse[i*8+e] = s[e];
}

// ---------------- SpMM + combine + bf16 split: one WARP per (dst, expert) ----------------
__global__ void k_spmm_combine(const float* __restrict__ bias) {
    int dst = blockIdx.x;
    int e = threadIdx.x >> 5;          // warp = expert
    int lane = threadIdx.x & 31;       // 8 channels per lane
    const float* vb = g_v + (size_t)e*NH + lane*8;
    int s0 = g_rowstart[dst], s1 = g_rowstart[dst+1];
    float a0=0.f,a1=0.f,a2=0.f,a3=0.f,a4=0.f,a5=0.f,a6=0.f,a7=0.f;
    for (int p = s0; p < s1; p++) {
        int src = g_csr_src[p];        // uniform within warp (broadcast)
        const float4* row = (const float4*)(vb + (size_t)src*256);
        float4 x0 = row[0], x1 = row[1];
        a0 += x0.x; a1 += x0.y; a2 += x0.z; a3 += x0.w;
        a4 += x1.x; a5 += x1.y; a6 += x1.z; a7 += x1.w;
    }
    size_t base = (size_t)e*NH + (size_t)dst*256 + lane*8;
    const float4* tb = (const float4*)(g_t + base);
    float4 t0 = tb[0], t1 = tb[1];
    const float4* bb = (const float4*)(bias + e*256 + lane*8);
    float4 b0 = bb[0], b1 = bb[1];
    float vals[8];
    vals[0]=t0.x+a0+b0.x; vals[1]=t0.y+a1+b0.y; vals[2]=t0.z+a2+b0.z; vals[3]=t0.w+a3+b0.w;
    vals[4]=t1.x+a4+b1.x; vals[5]=t1.y+a5+b1.y; vals[6]=t1.z+a6+b1.z; vals[7]=t1.w+a7+b1.w;
    union { __nv_bfloat16 h[8]; uint4 u; } H, L;
#pragma unroll
    for (int j = 0; j < 8; j++) {
        float v = fmaxf(vals[j], 0.f);
        __nv_bfloat16 hi = __float2bfloat16(v);
        H.h[j] = hi;
        L.h[j] = __float2bfloat16(v - __bfloat162float(hi));
    }
    *(uint4*)(g_Ah + base) = H.u;
    *(uint4*)(g_Al + base) = L.u;
}

// ---------------- output layer: one thread per (e,i), computes m0,m1,z0,z1 ----------------
__global__ void k_mz(const float* __restrict__ Wr, const float* __restrict__ Wn) {
    int idx = blockIdx.x*blockDim.x + threadIdx.x;
    if (idx >= NEx*Nn) return;
    int i = idx % Nn, e = idx / Nn;
    const uint4* ah = (const uint4*)(g_Ah + (size_t)e*NH + (size_t)i*256);
    const uint4* al = (const uint4*)(g_Al + (size_t)e*NH + (size_t)i*256);
    const float* WRe = Wr + e*512;
    const float* WNe = Wn + e*512;
    float m0=0.f, m1=0.f, z0=0.f, z1=0.f;
#pragma unroll 4
    for (int k8 = 0; k8 < 32; k8++) {
        uint4 vh = ah[k8], vl = al[k8];
        const __nv_bfloat16* ph = (const __nv_bfloat16*)&vh;
        const __nv_bfloat16* pl = (const __nv_bfloat16*)&vl;
#pragma unroll
        for (int j = 0; j < 8; j++) {
            float a = __bfloat162float(ph[j]) + __bfloat162float(pl[j]);
            int k = k8*8 + j;
            m0 += a*WRe[k*2];   m1 += a*WRe[k*2+1];
            z0 += a*WNe[k*2];   z1 += a*WNe[k*2+1];
        }
    }
    float* o = g_mz + (size_t)idx*4;
    o[0]=m0; o[1]=m1; o[2]=z0; o[3]=z1;
}

__global__ void k_aggz() {
    int idx = blockIdx.x*blockDim.x + threadIdx.x;
    if (idx >= NEx*Nn) return;
    int dst = idx % Nn;
    int e = idx / Nn;
    int s0 = g_rowstart[dst], s1 = g_rowstart[dst+1];
    float a0=0.f, a1=0.f;
    for (int p=s0; p<s1; p++) {
        int src = g_csr_src[p];
        const float* z = g_mz + ((size_t)e*Nn + src)*4 + 2;
        a0 += z[0]; a1 += z[1];
    }
    g_aggz[((size_t)e*Nn+dst)*2+0] = a0;
    g_aggz[((size_t)e*Nn+dst)*2+1] = a1;
}

__global__ void k_final(const float* __restrict__ outb, float* __restrict__ out) {
    int i = blockIdx.x*blockDim.x + threadIdx.x;
    if (i >= Nn) return;
    float o0=0.f, o1=0.f;
#pragma unroll
    for (int e=0;e<8;e++) {
        float s = g_sparse[i*8+e];
        const float* mz = g_mz + ((size_t)e*Nn+i)*4;
        const float* az = g_aggz + ((size_t)e*Nn+i)*2;
        o0 += s*(mz[0] + az[0] + outb[e*2+0]);
        o1 += s*(mz[1] + az[1] + outb[e*2+1]);
    }
    out[i*2+0] = o0;
    out[i*2+1] = o1;
}

// ---------------- launch ----------------
extern "C" void kernel_launch(void* const* d_in, const int* in_sizes, int n_in,
                              void* d_out, int out_size) {
    const float* x    = (const float*)d_in[0];
    const int*   ei   = (const int*)  d_in[1];
    const int*   batch= (const int*)  d_in[2];
    const float* encW = (const float*)d_in[3];
    const float* encb = (const float*)d_in[4];
    const float* rW1  = (const float*)d_in[5];
    const float* rb1  = (const float*)d_in[6];
    const float* rW2  = (const float*)d_in[7];
    const float* rb2  = (const float*)d_in[8];
    const float* hWr  = (const float*)d_in[9];
    const float* hWn  = (const float*)d_in[10];
    const float* hb   = (const float*)d_in[11];
    const float* oWr  = (const float*)d_in[12];
    const float* oWn  = (const float*)d_in[13];
    const float* ob   = (const float*)d_in[14];
    float* out = (float*)d_out;

    const int NTILES = (Nn + 127) / 128;   // 391
    dim3 gG(NTILES, 2, NEx*2);             // (mtile, ntile, e*2+mat)
    dim3 gS(Nn, 1, 1);                     // one warp per (dst, expert)

    k_zero<<<(Nn+255)/256,256>>>();
    k_encoder<<<(NH+255)/256,256>>>(x, encW, encb);
    k_convW<<<(NMATS*65536+255)/256,256>>>(rW1, hWr, hWn);
    k_hgemm<<<gG,256>>>(1, 1);             // layer 0 — sits at profiled launch slot
    k_count_nodes<<<256,256>>>(batch);
    k_count_edges<<<512,256>>>(ei, batch);
    k_indeg<<<(Ee+255)/256,256>>>(ei);
    k_sizefeat<<<(Nn+255)/256,256>>>(batch);
    k_scan1<<<(Nn+1023)/1024,1024>>>();
    k_scan2<<<1,64>>>();
    k_scan3<<<(Nn+255)/256,256>>>();
    k_cursor<<<(Nn+255)/256,256>>>();
    k_scatter<<<(Ee+255)/256,256>>>(ei);

    // router (exact fp32 in its own buffer g_rt)
    {
        dim3 gR((Nn+127)/128, 2, 1);
        k_sgemm_router<<<gR,256>>>(rW1);
        k_router_epi<<<(NH+255)/256,256>>>(rW1, rb1);
        k_logits<<<(Nn*NEx+255)/256,256>>>(rW2, rb2);
        k_topk<<<(Nn+255)/256,256>>>();
    }

    // hidden layers
    k_spmm_combine<<<gS,256>>>(hb + (size_t)0*NEx*Hh);          // layer 0 aggregate
    for (int l = 1; l < 3; l++) {
        k_hgemm<<<gG,256>>>(0, 1 + l*(NEx*2));
        k_spmm_combine<<<gS,256>>>(hb + (size_t)l*NEx*Hh);
    }

    // output layer
    k_mz<<<(NEx*Nn+255)/256,256>>>(oWr, oWn);
    k_aggz<<<(NEx*Nn+255)/256,256>>>();
    k_final<<<(Nn+255)/256,256>>>(ob, out);
}